// round 13
// baseline (speedup 1.0000x reference)
#include <cuda_runtime.h>
#include <stdint.h>
#include <math.h>

// ---------------------------------------------------------------------------
// Problem constants (G=256 grid, B=8 batches, 2048 samples)
// ---------------------------------------------------------------------------
#define NB 8            // batches
#define NM 16           // meshes = 8 pred + 8 targ
#define NV 65536        // vertices per mesh (G*G)
#define NS 2048         // samples per mesh
#define MAXF 131072     // capacity for faces (actual F = 130050)

// ---------------------------------------------------------------------------
// Scratch (static __device__ globals; no allocations allowed)
// ---------------------------------------------------------------------------
static __device__ float  g_logits[NM * MAXF];
static __device__ float  g_lmax[NM];
static __device__ int    g_fidx[NM * NS];
static __device__ float  g_samples[NM * NS * 3];
static __device__ double g_acc[4];               // 0:chamfer 1:edge 2:normal 3:lap
static __device__ float  g_nsum[NB * NV * 3];
static __device__ float  g_deg[NV];

struct Keys {
    unsigned kf0[NM], kf1[NM];   // categorical keys per mesh
    unsigned kb0[NM], kb1[NM];   // barycentric-uv keys per mesh
};

// ---------------------------------------------------------------------------
// Threefry-2x32 (exact JAX PRNG), host + device
// ---------------------------------------------------------------------------
__host__ __device__ __forceinline__ unsigned rotl32(unsigned x, int r) {
#ifdef __CUDA_ARCH__
    return __funnelshift_l(x, x, r);
#else
    return (x << r) | (x >> (32 - r));
#endif
}

__host__ __device__ __forceinline__ void tf2x32(unsigned k0, unsigned k1,
                                                unsigned c0, unsigned c1,
                                                unsigned &o0, unsigned &o1) {
    unsigned ks2 = k0 ^ k1 ^ 0x1BD11BDAu;
    unsigned x0 = c0 + k0, x1 = c1 + k1;
#define TFR(r) { x0 += x1; x1 = rotl32(x1, r); x1 ^= x0; }
    TFR(13) TFR(15) TFR(26) TFR(6)
    x0 += k1;  x1 += ks2 + 1u;
    TFR(17) TFR(29) TFR(16) TFR(24)
    x0 += ks2; x1 += k0 + 2u;
    TFR(13) TFR(15) TFR(26) TFR(6)
    x0 += k0;  x1 += k1 + 3u;
    TFR(17) TFR(29) TFR(16) TFR(24)
    x0 += k1;  x1 += ks2 + 4u;
    TFR(13) TFR(15) TFR(26) TFR(6)
    x0 += ks2; x1 += k0 + 5u;
#undef TFR
    o0 = x0; o1 = x1;
}

// Partitionable-mode 32-bit draw: counter (0, idx), output = o0 ^ o1.
__device__ __forceinline__ unsigned tf_bits32(unsigned k0, unsigned k1, unsigned idx) {
    unsigned o0, o1;
    tf2x32(k0, k1, 0u, idx, o0, o1);
    return o0 ^ o1;
}

__device__ __forceinline__ float bits_to_unit(unsigned b) {
    // JAX uniform bit manipulation: (bits>>9 | 0x3f800000) as float - 1
    return __uint_as_float((b >> 9) | 0x3f800000u) - 1.0f;
}

// ---------------------------------------------------------------------------
// Generic double block reduce (blockDim.x == 256)
// ---------------------------------------------------------------------------
__device__ double blockReduceSum(double v) {
    __shared__ double sm[32];
    int lane = threadIdx.x & 31, wid = threadIdx.x >> 5;
    for (int o = 16; o > 0; o >>= 1) v += __shfl_down_sync(0xffffffffu, v, o);
    if (lane == 0) sm[wid] = v;
    __syncthreads();
    v = (threadIdx.x < 8) ? sm[threadIdx.x] : 0.0;
    if (wid == 0)
        for (int o = 4; o > 0; o >>= 1) v += __shfl_down_sync(0xffffffffu, v, o);
    return v;
}

// ---------------------------------------------------------------------------
// K0: zero accumulators + laplacian scratch
// ---------------------------------------------------------------------------
__global__ void k_zero() {
    int i = blockIdx.x * blockDim.x + threadIdx.x;
    int stride = gridDim.x * blockDim.x;
    if (i < 4) g_acc[i] = 0.0;
    for (int t = i; t < NB * NV * 3; t += stride) g_nsum[t] = 0.0f;
    for (int t = i; t < NV; t += stride) g_deg[t] = 0.0f;
}

// ---------------------------------------------------------------------------
// K1: per-mesh per-face log(area + 1e-12)
// ---------------------------------------------------------------------------
__global__ void k_logits(const float* __restrict__ vp, const float* __restrict__ vt,
                         const int* __restrict__ faces, int F) {
    int f = blockIdx.x * blockDim.x + threadIdx.x;
    int m = blockIdx.y;
    if (f >= F) return;
    const float* v = (m < NB) ? (vp + (size_t)m * NV * 3)
                              : (vt + (size_t)(m - NB) * NV * 3);
    int a = faces[3*f], b = faces[3*f+1], c = faces[3*f+2];
    float ax = v[3*a], ay = v[3*a+1], az = v[3*a+2];
    float e1x = v[3*b]-ax, e1y = v[3*b+1]-ay, e1z = v[3*b+2]-az;
    float e2x = v[3*c]-ax, e2y = v[3*c+1]-ay, e2z = v[3*c+2]-az;
    float cx = e1y*e2z - e1z*e2y;
    float cy = e1z*e2x - e1x*e2z;
    float cz = e1x*e2y - e1y*e2x;
    float area = 0.5f * sqrtf(cx*cx + cy*cy + cz*cz);
    g_logits[m * MAXF + f] = logf(area + 1e-12f);
}

// K1b: per-mesh max logit
__global__ void k_lmax(int F) {
    __shared__ float sm[256];
    int m = blockIdx.x;
    float mx = -INFINITY;
    for (int f = threadIdx.x; f < F; f += 256) mx = fmaxf(mx, g_logits[m*MAXF + f]);
    sm[threadIdx.x] = mx; __syncthreads();
    for (int o = 128; o > 0; o >>= 1) {
        if (threadIdx.x < o) sm[threadIdx.x] = fmaxf(sm[threadIdx.x], sm[threadIdx.x + o]);
        __syncthreads();
    }
    if (threadIdx.x == 0) g_lmax[m] = sm[0];
}

// ---------------------------------------------------------------------------
// K2: categorical sampling — THE hot kernel (partitionable threefry).
// One block per (mesh m, row i in [0,2048)). Element (i,f) draws bits from
// counter (0, i*F+f), bits = o0^o1. Gumbel logs skipped via conservative
// u-threshold; exact -log(-log u) + logit only for candidates.
//
// Measured-optimum configuration (R3/R12, 15.8 ms). Nine controlled variants
// (pipe rebalancing, wide-multiply rotates, dual-stream ILP, injection
// folding, integer/grouped screens) all conserved total issued work
// (~66 instr/elem; 60 irreducible threefry ops) and were neutral-or-worse.
// Binding resource: alu pipe @ 88% of elapsed. This round's single change:
// unroll 4 -> 8, halving branch/loop overhead and doubling the scheduler's
// straight-line packing window, probing the residual 12% non-alu bubble.
// ---------------------------------------------------------------------------
__global__ __launch_bounds__(256) void k_categorical(Keys keys, int F) {
    int bid = blockIdx.x;
    int m = bid >> 11;          // 2048 rows per mesh
    int i = bid & 2047;
    unsigned k0 = keys.kf0[m], k1 = keys.kf1[m];
    const float* __restrict__ logits = g_logits + m * MAXF;
    float lmax = g_lmax[m];
    unsigned base = (unsigned)i * (unsigned)F;
    const float TINY = 1.1754944e-38f;

    float best = -INFINITY;
    int bf = 0;
    float uth = -1.0f;

#pragma unroll 8
    for (int f = threadIdx.x; f < F; f += 256) {
        unsigned bits = tf_bits32(k0, k1, base + (unsigned)f);
        float u = bits_to_unit(bits);
        if (u > uth) {
            float s = -logf(-logf(fmaxf(u, TINY))) + logits[f];
            if (s > best) {
                best = s; bf = f;
                float t = best - lmax - 1e-3f;
                uth = (t >= 16.0f) ? 1.0f : (expf(-expf(-t)) - 8e-6f);
            }
        }
    }

    __shared__ float sv[256];
    __shared__ int   si[256];
    sv[threadIdx.x] = best; si[threadIdx.x] = bf;
    __syncthreads();
    for (int o = 128; o > 0; o >>= 1) {
        if (threadIdx.x < o) {
            float v2 = sv[threadIdx.x + o]; int i2 = si[threadIdx.x + o];
            if (v2 > sv[threadIdx.x] ||
                (v2 == sv[threadIdx.x] && i2 < si[threadIdx.x])) {
                sv[threadIdx.x] = v2; si[threadIdx.x] = i2;
            }
        }
        __syncthreads();
    }
    if (threadIdx.x == 0) g_fidx[m * NS + i] = si[0];
}

// ---------------------------------------------------------------------------
// K3: barycentric uv draws + point sampling (partitionable threefry)
// ---------------------------------------------------------------------------
__global__ void k_sample(Keys keys, const float* __restrict__ vp,
                         const float* __restrict__ vt, const int* __restrict__ faces) {
    int idx = blockIdx.x * blockDim.x + threadIdx.x;
    if (idx >= NM * NS) return;
    int m = idx / NS, s = idx % NS;
    unsigned k0 = keys.kb0[m], k1 = keys.kb1[m];
    // uv element (s, e) has flat index 2s+e in the (2048, 2) stream
    float u0 = bits_to_unit(tf_bits32(k0, k1, 2u * (unsigned)s));
    float u1 = bits_to_unit(tf_bits32(k0, k1, 2u * (unsigned)s + 1u));
    float su = sqrtf(u0);
    float w0 = 1.0f - su, w1 = su * (1.0f - u1), w2 = su * u1;
    int f = g_fidx[idx];
    const float* v = (m < NB) ? (vp + (size_t)m * NV * 3)
                              : (vt + (size_t)(m - NB) * NV * 3);
    int a = faces[3*f], b = faces[3*f+1], c = faces[3*f+2];
#pragma unroll
    for (int d = 0; d < 3; d++)
        g_samples[idx*3 + d] = w0 * v[3*a+d] + w1 * v[3*b+d] + w2 * v[3*c+d];
}

// ---------------------------------------------------------------------------
// K4: chamfer (both directions via blockIdx.y)
// ---------------------------------------------------------------------------
__global__ __launch_bounds__(256) void k_chamfer() {
    __shared__ float ys[NS * 3];
    int b = blockIdx.x, dir = blockIdx.y, chunk = blockIdx.z;
    int mx = (dir == 0) ? b : b + NB;
    int my = (dir == 0) ? b + NB : b;
    const float* X = g_samples + (size_t)mx * NS * 3;
    const float* Y = g_samples + (size_t)my * NS * 3;
    for (int t = threadIdx.x; t < NS * 3; t += 256) ys[t] = Y[t];
    __syncthreads();
    int s = chunk * 256 + threadIdx.x;
    float x0 = X[3*s], x1 = X[3*s+1], x2 = X[3*s+2];
    float mn = INFINITY;
    for (int j = 0; j < NS; j++) {
        float d0 = x0 - ys[3*j], d1 = x1 - ys[3*j+1], d2 = x2 - ys[3*j+2];
        mn = fminf(mn, d0*d0 + d1*d1 + d2*d2);
    }
    double v = blockReduceSum((double)mn);
    if (threadIdx.x == 0) atomicAdd(&g_acc[0], v);
}

// ---------------------------------------------------------------------------
// K5: edge loss
// ---------------------------------------------------------------------------
__global__ void k_edge(const float* __restrict__ vp, const int* __restrict__ edges, int E) {
    long total = (long)NB * E;
    double local = 0.0;
    for (long idx = (long)blockIdx.x * blockDim.x + threadIdx.x; idx < total;
         idx += (long)gridDim.x * blockDim.x) {
        int b = (int)(idx / E), e = (int)(idx % E);
        const float* v = vp + (size_t)b * NV * 3;
        int e0 = edges[2*e], e1 = edges[2*e+1];
        float dx = v[3*e0]-v[3*e1], dy = v[3*e0+1]-v[3*e1+1], dz = v[3*e0+2]-v[3*e1+2];
        local += (double)(dx*dx + dy*dy + dz*dz);
    }
    double v = blockReduceSum(local);
    if (threadIdx.x == 0) atomicAdd(&g_acc[1], v);
}

// ---------------------------------------------------------------------------
// K6: normal consistency
// ---------------------------------------------------------------------------
__global__ void k_normal(const float* __restrict__ vp, const int* __restrict__ ncp, int P) {
    long total = (long)NB * P;
    double local = 0.0;
    for (long idx = (long)blockIdx.x * blockDim.x + threadIdx.x; idx < total;
         idx += (long)gridDim.x * blockDim.x) {
        int b = (int)(idx / P), p = (int)(idx % P);
        const float* v = vp + (size_t)b * NV * 3;
        int i0 = ncp[4*p], i1 = ncp[4*p+1], ia = ncp[4*p+2], ib = ncp[4*p+3];
        float v0x = v[3*i0], v0y = v[3*i0+1], v0z = v[3*i0+2];
        float ex = v[3*i1]-v0x, ey = v[3*i1+1]-v0y, ez = v[3*i1+2]-v0z;
        float Ax = v[3*ia]-v0x, Ay = v[3*ia+1]-v0y, Az = v[3*ia+2]-v0z;
        float Bx = v[3*ib]-v0x, By = v[3*ib+1]-v0y, Bz = v[3*ib+2]-v0z;
        float n0x = ey*Az - ez*Ay, n0y = ez*Ax - ex*Az, n0z = ex*Ay - ey*Ax;
        float c1x = ey*Bz - ez*By, c1y = ez*Bx - ex*Bz, c1z = ex*By - ey*Bx;
        float dot = -(n0x*c1x + n0y*c1y + n0z*c1z);   // n1 = -cross(e, b-v0)
        float l0 = sqrtf(n0x*n0x + n0y*n0y + n0z*n0z);
        float l1 = sqrtf(c1x*c1x + c1y*c1y + c1z*c1z);
        float cosv = dot / (fmaxf(l0, 1e-8f) * fmaxf(l1, 1e-8f));
        local += (double)(1.0f - cosv);
    }
    double v = blockReduceSum(local);
    if (threadIdx.x == 0) atomicAdd(&g_acc[2], v);
}

// ---------------------------------------------------------------------------
// K7/K8: uniform laplacian
// ---------------------------------------------------------------------------
__global__ void k_lap_scatter(const float* __restrict__ vp, const int* __restrict__ edges, int E) {
    long total = (long)NB * E;
    for (long idx = (long)blockIdx.x * blockDim.x + threadIdx.x; idx < total;
         idx += (long)gridDim.x * blockDim.x) {
        int b = (int)(idx / E), e = (int)(idx % E);
        int e0 = edges[2*e], e1 = edges[2*e+1];
        const float* v = vp + (size_t)b * NV * 3;
#pragma unroll
        for (int c = 0; c < 3; c++) {
            atomicAdd(&g_nsum[((size_t)b*NV + e0)*3 + c], v[3*e1 + c]);
            atomicAdd(&g_nsum[((size_t)b*NV + e1)*3 + c], v[3*e0 + c]);
        }
        if (b == 0) {
            atomicAdd(&g_deg[e0], 1.0f);
            atomicAdd(&g_deg[e1], 1.0f);
        }
    }
}

__global__ void k_lap_reduce(const float* __restrict__ vp) {
    long total = (long)NB * NV;
    double local = 0.0;
    for (long idx = (long)blockIdx.x * blockDim.x + threadIdx.x; idx < total;
         idx += (long)gridDim.x * blockDim.x) {
        int b = (int)(idx / NV), vi = (int)(idx % NV);
        float dg = fmaxf(g_deg[vi], 1.0f);
        const float* v = vp + ((size_t)b * NV + vi) * 3;
        const float* ns = g_nsum + ((size_t)b * NV + vi) * 3;
        float lx = ns[0]/dg - v[0];
        float ly = ns[1]/dg - v[1];
        float lz = ns[2]/dg - v[2];
        local += (double)sqrtf(lx*lx + ly*ly + lz*lz);
    }
    double v = blockReduceSum(local);
    if (threadIdx.x == 0) atomicAdd(&g_acc[3], v);
}

// ---------------------------------------------------------------------------
// K9: finalize
// ---------------------------------------------------------------------------
__global__ void k_final(float* out, int E, int P) {
    double ch = g_acc[0] / (double)(NB * NS);       // both direction means summed
    double ed = g_acc[1] / ((double)NB * (double)E);
    double nr = g_acc[2] / ((double)NB * (double)P);
    double lp = g_acc[3] / ((double)NB * (double)NV);
    out[0] = (float)(ch + ed + 0.1 * nr + 0.1 * lp);
    out[1] = (float)ch;
    out[2] = (float)ed;
    out[3] = (float)nr;
    out[4] = (float)lp;
}

// ---------------------------------------------------------------------------
// Host: JAX key derivation, PARTITIONABLE threefry semantics:
//   fold_in(key, d)     = tf(key, (0, d))            -> (o0, o1)
//   split(key, n)[i]    = tf(key, (0, i))            -> (o0, o1)   (fold-like)
//   random_bits32[i]    = o0 ^ o1 of tf(key, (0, i))
// ---------------------------------------------------------------------------
extern "C" void kernel_launch(void* const* d_in, const int* in_sizes, int n_in,
                              void* d_out, int out_size) {
    const float* vp    = (const float*)d_in[0];
    const float* vt    = (const float*)d_in[1];
    const int*   faces = (const int*)d_in[2];
    const int*   edges = (const int*)d_in[3];
    const int*   ncp   = (const int*)d_in[4];
    int F = in_sizes[2] / 3;
    int E = in_sizes[3] / 2;
    int P = in_sizes[4] / 4;

    Keys keys;
    // skey = key(42) -> (0, 42); fold_in(skey, 0/1)
    unsigned pk0, pk1, tk0, tk1;
    tf2x32(0u, 42u, 0u, 0u, pk0, pk1);
    tf2x32(0u, 42u, 0u, 1u, tk0, tk1);
    for (int grp = 0; grp < 2; grp++) {
        unsigned K0 = grp ? tk0 : pk0;
        unsigned K1 = grp ? tk1 : pk1;
        for (int b = 0; b < 8; b++) {
            // split(key, 8)[b] = tf(key, (0, b))  (fold-like split)
            unsigned mk0, mk1;
            tf2x32(K0, K1, 0u, (unsigned)b, mk0, mk1);
            // kf, kb = split(mesh_key, 2)
            unsigned f0, f1, b0, b1;
            tf2x32(mk0, mk1, 0u, 0u, f0, f1);
            tf2x32(mk0, mk1, 0u, 1u, b0, b1);
            int m = grp * 8 + b;
            keys.kf0[m] = f0; keys.kf1[m] = f1;
            keys.kb0[m] = b0; keys.kb1[m] = b1;
        }
    }

    k_zero<<<512, 256>>>();
    dim3 glog((F + 255) / 256, NM);
    k_logits<<<glog, 256>>>(vp, vt, faces, F);
    k_lmax<<<NM, 256>>>(F);
    k_categorical<<<NM * NS, 256>>>(keys, F);
    k_sample<<<(NM * NS + 255) / 256, 256>>>(keys, vp, vt, faces);
    k_chamfer<<<dim3(NB, 2, NS / 256), 256>>>();
    k_edge<<<2048, 256>>>(vp, edges, E);
    k_normal<<<2048, 256>>>(vp, ncp, P);
    k_lap_scatter<<<2048, 256>>>(vp, edges, E);
    k_lap_reduce<<<2048, 256>>>(vp);
    k_final<<<1, 1>>>((float*)d_out, E, P);
}

// round 14
// speedup vs baseline: 1.2581x; 1.2581x over previous
#include <cuda_runtime.h>
#include <stdint.h>
#include <math.h>

// ---------------------------------------------------------------------------
// Problem constants (G=256 grid, B=8 batches, 2048 samples)
// ---------------------------------------------------------------------------
#define NB 8            // batches
#define NM 16           // meshes = 8 pred + 8 targ
#define NV 65536        // vertices per mesh (G*G)
#define NS 2048         // samples per mesh
#define MAXF 131072     // capacity for faces (actual F = 130050)

// ---------------------------------------------------------------------------
// Scratch (static __device__ globals; no allocations allowed)
// ---------------------------------------------------------------------------
static __device__ float  g_logits[NM * MAXF];
static __device__ float  g_lmax[NM];
static __device__ int    g_fidx[NM * NS];
static __device__ float  g_samples[NM * NS * 3];
static __device__ double g_acc[4];               // 0:chamfer 1:edge 2:normal 3:lap
static __device__ float  g_nsum[NB * NV * 3];
static __device__ float  g_deg[NV];

struct Keys {
    unsigned kf0[NM], kf1[NM];   // categorical keys per mesh
    unsigned kb0[NM], kb1[NM];   // barycentric-uv keys per mesh
};

// ---------------------------------------------------------------------------
// Threefry-2x32 (exact JAX PRNG), host + device
// ---------------------------------------------------------------------------
__host__ __device__ __forceinline__ unsigned rotl32(unsigned x, int r) {
#ifdef __CUDA_ARCH__
    return __funnelshift_l(x, x, r);
#else
    return (x << r) | (x >> (32 - r));
#endif
}

__host__ __device__ __forceinline__ void tf2x32(unsigned k0, unsigned k1,
                                                unsigned c0, unsigned c1,
                                                unsigned &o0, unsigned &o1) {
    unsigned ks2 = k0 ^ k1 ^ 0x1BD11BDAu;
    unsigned x0 = c0 + k0, x1 = c1 + k1;
#define TFR(r) { x0 += x1; x1 = rotl32(x1, r); x1 ^= x0; }
    TFR(13) TFR(15) TFR(26) TFR(6)
    x0 += k1;  x1 += ks2 + 1u;
    TFR(17) TFR(29) TFR(16) TFR(24)
    x0 += ks2; x1 += k0 + 2u;
    TFR(13) TFR(15) TFR(26) TFR(6)
    x0 += k0;  x1 += k1 + 3u;
    TFR(17) TFR(29) TFR(16) TFR(24)
    x0 += k1;  x1 += ks2 + 4u;
    TFR(13) TFR(15) TFR(26) TFR(6)
    x0 += ks2; x1 += k0 + 5u;
#undef TFR
    o0 = x0; o1 = x1;
}

// Partitionable-mode 32-bit draw: counter (0, idx), output = o0 ^ o1.
__device__ __forceinline__ unsigned tf_bits32(unsigned k0, unsigned k1, unsigned idx) {
    unsigned o0, o1;
    tf2x32(k0, k1, 0u, idx, o0, o1);
    return o0 ^ o1;
}

__device__ __forceinline__ float bits_to_unit(unsigned b) {
    // JAX uniform bit manipulation: (bits>>9 | 0x3f800000) as float - 1
    return __uint_as_float((b >> 9) | 0x3f800000u) - 1.0f;
}

// ---------------------------------------------------------------------------
// Generic double block reduce (blockDim.x == 256)
// ---------------------------------------------------------------------------
__device__ double blockReduceSum(double v) {
    __shared__ double sm[32];
    int lane = threadIdx.x & 31, wid = threadIdx.x >> 5;
    for (int o = 16; o > 0; o >>= 1) v += __shfl_down_sync(0xffffffffu, v, o);
    if (lane == 0) sm[wid] = v;
    __syncthreads();
    v = (threadIdx.x < 8) ? sm[threadIdx.x] : 0.0;
    if (wid == 0)
        for (int o = 4; o > 0; o >>= 1) v += __shfl_down_sync(0xffffffffu, v, o);
    return v;
}

// ---------------------------------------------------------------------------
// K0: zero accumulators + laplacian scratch
// ---------------------------------------------------------------------------
__global__ void k_zero() {
    int i = blockIdx.x * blockDim.x + threadIdx.x;
    int stride = gridDim.x * blockDim.x;
    if (i < 4) g_acc[i] = 0.0;
    for (int t = i; t < NB * NV * 3; t += stride) g_nsum[t] = 0.0f;
    for (int t = i; t < NV; t += stride) g_deg[t] = 0.0f;
}

// ---------------------------------------------------------------------------
// K1: per-mesh per-face log(area + 1e-12)
// ---------------------------------------------------------------------------
__global__ void k_logits(const float* __restrict__ vp, const float* __restrict__ vt,
                         const int* __restrict__ faces, int F) {
    int f = blockIdx.x * blockDim.x + threadIdx.x;
    int m = blockIdx.y;
    if (f >= F) return;
    const float* v = (m < NB) ? (vp + (size_t)m * NV * 3)
                              : (vt + (size_t)(m - NB) * NV * 3);
    int a = faces[3*f], b = faces[3*f+1], c = faces[3*f+2];
    float ax = v[3*a], ay = v[3*a+1], az = v[3*a+2];
    float e1x = v[3*b]-ax, e1y = v[3*b+1]-ay, e1z = v[3*b+2]-az;
    float e2x = v[3*c]-ax, e2y = v[3*c+1]-ay, e2z = v[3*c+2]-az;
    float cx = e1y*e2z - e1z*e2y;
    float cy = e1z*e2x - e1x*e2z;
    float cz = e1x*e2y - e1y*e2x;
    float area = 0.5f * sqrtf(cx*cx + cy*cy + cz*cz);
    g_logits[m * MAXF + f] = logf(area + 1e-12f);
}

// K1b: per-mesh max logit
__global__ void k_lmax(int F) {
    __shared__ float sm[256];
    int m = blockIdx.x;
    float mx = -INFINITY;
    for (int f = threadIdx.x; f < F; f += 256) mx = fmaxf(mx, g_logits[m*MAXF + f]);
    sm[threadIdx.x] = mx; __syncthreads();
    for (int o = 128; o > 0; o >>= 1) {
        if (threadIdx.x < o) sm[threadIdx.x] = fmaxf(sm[threadIdx.x], sm[threadIdx.x + o]);
        __syncthreads();
    }
    if (threadIdx.x == 0) g_lmax[m] = sm[0];
}

// ---------------------------------------------------------------------------
// K2: categorical sampling — THE hot kernel (partitionable threefry).
// One block per (mesh m, row i in [0,2048)). Element (i,f) draws bits from
// counter (0, i*F+f), bits = o0^o1.
//
// WARP-SHARED SCREEN: the candidate path (2x logf + threshold update, ~40
// instr) executes at warp granularity whenever ANY lane passes its private
// threshold — ~120 of 508 iterations with private thresholds (~13% of issued
// work). Every 16 iterations we butterfly-max `best` across the warp and
// recompute uth from the WARP best. Since uth is monotone in best and
// warp-best >= own best, the shared threshold is always >= the private one:
// strictly fewer candidate entries, still conservative (any element within
// the 1e-3 margin of warp best — including exact ties — passes, preserving
// first-max tie-breaking exactly). Chunks are warp-uniform (nmin = F/256
// iterations for every thread; <=1-element per-thread tail after).
// ---------------------------------------------------------------------------
__global__ __launch_bounds__(256) void k_categorical(Keys keys, int F) {
    int bid = blockIdx.x;
    int m = bid >> 11;          // 2048 rows per mesh
    int i = bid & 2047;
    unsigned k0 = keys.kf0[m], k1 = keys.kf1[m];
    const float* __restrict__ logits = g_logits + m * MAXF;
    float lmax = g_lmax[m];
    unsigned base = (unsigned)i * (unsigned)F;
    const float TINY = 1.1754944e-38f;

    float best = -INFINITY;
    int bf = 0;
    float uth = -1.0f;

// one element; updates best/bf and the private uth on new records
#define ELEM(ff) { \
    unsigned bits = tf_bits32(k0, k1, base + (unsigned)(ff)); \
    float u = bits_to_unit(bits); \
    if (u > uth) { \
        float s = -logf(-logf(fmaxf(u, TINY))) + logits[(ff)]; \
        if (s > best) { \
            best = s; bf = (ff); \
            float t = best - lmax - 1e-3f; \
            uth = (t >= 16.0f) ? 1.0f : (expf(-expf(-t)) - 8e-6f); \
        } \
    } }

    int nmin = F >> 8;          // floor(F/256): iterations ALL threads have
    int nchunk = nmin >> 4;     // full 16-iteration warp-uniform chunks
    int rem = nmin & 15;
    int f = threadIdx.x;

    for (int c = 0; c < nchunk; ++c) {
#pragma unroll 4
        for (int j = 0; j < 16; ++j, f += 256) ELEM(f);
        // warp-shared threshold refresh (full warp active: chunks uniform)
        float wb = best;
#pragma unroll
        for (int o = 16; o > 0; o >>= 1)
            wb = fmaxf(wb, __shfl_xor_sync(0xffffffffu, wb, o));
        float t = wb - lmax - 1e-3f;
        uth = (t >= 16.0f) ? 1.0f : (expf(-expf(-t)) - 8e-6f);
    }
#pragma unroll 4
    for (int j = 0; j < rem; ++j, f += 256) ELEM(f);
    for (; f < F; f += 256) ELEM(f);   // per-thread tail (<=1 element)
#undef ELEM

    __shared__ float sv[256];
    __shared__ int   si[256];
    sv[threadIdx.x] = best; si[threadIdx.x] = bf;
    __syncthreads();
    for (int o = 128; o > 0; o >>= 1) {
        if (threadIdx.x < o) {
            float v2 = sv[threadIdx.x + o]; int i2 = si[threadIdx.x + o];
            if (v2 > sv[threadIdx.x] ||
                (v2 == sv[threadIdx.x] && i2 < si[threadIdx.x])) {
                sv[threadIdx.x] = v2; si[threadIdx.x] = i2;
            }
        }
        __syncthreads();
    }
    if (threadIdx.x == 0) g_fidx[m * NS + i] = si[0];
}

// ---------------------------------------------------------------------------
// K3: barycentric uv draws + point sampling (partitionable threefry)
// ---------------------------------------------------------------------------
__global__ void k_sample(Keys keys, const float* __restrict__ vp,
                         const float* __restrict__ vt, const int* __restrict__ faces) {
    int idx = blockIdx.x * blockDim.x + threadIdx.x;
    if (idx >= NM * NS) return;
    int m = idx / NS, s = idx % NS;
    unsigned k0 = keys.kb0[m], k1 = keys.kb1[m];
    // uv element (s, e) has flat index 2s+e in the (2048, 2) stream
    float u0 = bits_to_unit(tf_bits32(k0, k1, 2u * (unsigned)s));
    float u1 = bits_to_unit(tf_bits32(k0, k1, 2u * (unsigned)s + 1u));
    float su = sqrtf(u0);
    float w0 = 1.0f - su, w1 = su * (1.0f - u1), w2 = su * u1;
    int f = g_fidx[idx];
    const float* v = (m < NB) ? (vp + (size_t)m * NV * 3)
                              : (vt + (size_t)(m - NB) * NV * 3);
    int a = faces[3*f], b = faces[3*f+1], c = faces[3*f+2];
#pragma unroll
    for (int d = 0; d < 3; d++)
        g_samples[idx*3 + d] = w0 * v[3*a+d] + w1 * v[3*b+d] + w2 * v[3*c+d];
}

// ---------------------------------------------------------------------------
// K4: chamfer (both directions via blockIdx.y)
// ---------------------------------------------------------------------------
__global__ __launch_bounds__(256) void k_chamfer() {
    __shared__ float ys[NS * 3];
    int b = blockIdx.x, dir = blockIdx.y, chunk = blockIdx.z;
    int mx = (dir == 0) ? b : b + NB;
    int my = (dir == 0) ? b + NB : b;
    const float* X = g_samples + (size_t)mx * NS * 3;
    const float* Y = g_samples + (size_t)my * NS * 3;
    for (int t = threadIdx.x; t < NS * 3; t += 256) ys[t] = Y[t];
    __syncthreads();
    int s = chunk * 256 + threadIdx.x;
    float x0 = X[3*s], x1 = X[3*s+1], x2 = X[3*s+2];
    float mn = INFINITY;
    for (int j = 0; j < NS; j++) {
        float d0 = x0 - ys[3*j], d1 = x1 - ys[3*j+1], d2 = x2 - ys[3*j+2];
        mn = fminf(mn, d0*d0 + d1*d1 + d2*d2);
    }
    double v = blockReduceSum((double)mn);
    if (threadIdx.x == 0) atomicAdd(&g_acc[0], v);
}

// ---------------------------------------------------------------------------
// K5: edge loss
// ---------------------------------------------------------------------------
__global__ void k_edge(const float* __restrict__ vp, const int* __restrict__ edges, int E) {
    long total = (long)NB * E;
    double local = 0.0;
    for (long idx = (long)blockIdx.x * blockDim.x + threadIdx.x; idx < total;
         idx += (long)gridDim.x * blockDim.x) {
        int b = (int)(idx / E), e = (int)(idx % E);
        const float* v = vp + (size_t)b * NV * 3;
        int e0 = edges[2*e], e1 = edges[2*e+1];
        float dx = v[3*e0]-v[3*e1], dy = v[3*e0+1]-v[3*e1+1], dz = v[3*e0+2]-v[3*e1+2];
        local += (double)(dx*dx + dy*dy + dz*dz);
    }
    double v = blockReduceSum(local);
    if (threadIdx.x == 0) atomicAdd(&g_acc[1], v);
}

// ---------------------------------------------------------------------------
// K6: normal consistency
// ---------------------------------------------------------------------------
__global__ void k_normal(const float* __restrict__ vp, const int* __restrict__ ncp, int P) {
    long total = (long)NB * P;
    double local = 0.0;
    for (long idx = (long)blockIdx.x * blockDim.x + threadIdx.x; idx < total;
         idx += (long)gridDim.x * blockDim.x) {
        int b = (int)(idx / P), p = (int)(idx % P);
        const float* v = vp + (size_t)b * NV * 3;
        int i0 = ncp[4*p], i1 = ncp[4*p+1], ia = ncp[4*p+2], ib = ncp[4*p+3];
        float v0x = v[3*i0], v0y = v[3*i0+1], v0z = v[3*i0+2];
        float ex = v[3*i1]-v0x, ey = v[3*i1+1]-v0y, ez = v[3*i1+2]-v0z;
        float Ax = v[3*ia]-v0x, Ay = v[3*ia+1]-v0y, Az = v[3*ia+2]-v0z;
        float Bx = v[3*ib]-v0x, By = v[3*ib+1]-v0y, Bz = v[3*ib+2]-v0z;
        float n0x = ey*Az - ez*Ay, n0y = ez*Ax - ex*Az, n0z = ex*Ay - ey*Ax;
        float c1x = ey*Bz - ez*By, c1y = ez*Bx - ex*Bz, c1z = ex*By - ey*Bx;
        float dot = -(n0x*c1x + n0y*c1y + n0z*c1z);   // n1 = -cross(e, b-v0)
        float l0 = sqrtf(n0x*n0x + n0y*n0y + n0z*n0z);
        float l1 = sqrtf(c1x*c1x + c1y*c1y + c1z*c1z);
        float cosv = dot / (fmaxf(l0, 1e-8f) * fmaxf(l1, 1e-8f));
        local += (double)(1.0f - cosv);
    }
    double v = blockReduceSum(local);
    if (threadIdx.x == 0) atomicAdd(&g_acc[2], v);
}

// ---------------------------------------------------------------------------
// K7/K8: uniform laplacian
// ---------------------------------------------------------------------------
__global__ void k_lap_scatter(const float* __restrict__ vp, const int* __restrict__ edges, int E) {
    long total = (long)NB * E;
    for (long idx = (long)blockIdx.x * blockDim.x + threadIdx.x; idx < total;
         idx += (long)gridDim.x * blockDim.x) {
        int b = (int)(idx / E), e = (int)(idx % E);
        int e0 = edges[2*e], e1 = edges[2*e+1];
        const float* v = vp + (size_t)b * NV * 3;
#pragma unroll
        for (int c = 0; c < 3; c++) {
            atomicAdd(&g_nsum[((size_t)b*NV + e0)*3 + c], v[3*e1 + c]);
            atomicAdd(&g_nsum[((size_t)b*NV + e1)*3 + c], v[3*e0 + c]);
        }
        if (b == 0) {
            atomicAdd(&g_deg[e0], 1.0f);
            atomicAdd(&g_deg[e1], 1.0f);
        }
    }
}

__global__ void k_lap_reduce(const float* __restrict__ vp) {
    long total = (long)NB * NV;
    double local = 0.0;
    for (long idx = (long)blockIdx.x * blockDim.x + threadIdx.x; idx < total;
         idx += (long)gridDim.x * blockDim.x) {
        int b = (int)(idx / NV), vi = (int)(idx % NV);
        float dg = fmaxf(g_deg[vi], 1.0f);
        const float* v = vp + ((size_t)b * NV + vi) * 3;
        const float* ns = g_nsum + ((size_t)b * NV + vi) * 3;
        float lx = ns[0]/dg - v[0];
        float ly = ns[1]/dg - v[1];
        float lz = ns[2]/dg - v[2];
        local += (double)sqrtf(lx*lx + ly*ly + lz*lz);
    }
    double v = blockReduceSum(local);
    if (threadIdx.x == 0) atomicAdd(&g_acc[3], v);
}

// ---------------------------------------------------------------------------
// K9: finalize
// ---------------------------------------------------------------------------
__global__ void k_final(float* out, int E, int P) {
    double ch = g_acc[0] / (double)(NB * NS);       // both direction means summed
    double ed = g_acc[1] / ((double)NB * (double)E);
    double nr = g_acc[2] / ((double)NB * (double)P);
    double lp = g_acc[3] / ((double)NB * (double)NV);
    out[0] = (float)(ch + ed + 0.1 * nr + 0.1 * lp);
    out[1] = (float)ch;
    out[2] = (float)ed;
    out[3] = (float)nr;
    out[4] = (float)lp;
}

// ---------------------------------------------------------------------------
// Host: JAX key derivation, PARTITIONABLE threefry semantics:
//   fold_in(key, d)     = tf(key, (0, d))            -> (o0, o1)
//   split(key, n)[i]    = tf(key, (0, i))            -> (o0, o1)   (fold-like)
//   random_bits32[i]    = o0 ^ o1 of tf(key, (0, i))
// ---------------------------------------------------------------------------
extern "C" void kernel_launch(void* const* d_in, const int* in_sizes, int n_in,
                              void* d_out, int out_size) {
    const float* vp    = (const float*)d_in[0];
    const float* vt    = (const float*)d_in[1];
    const int*   faces = (const int*)d_in[2];
    const int*   edges = (const int*)d_in[3];
    const int*   ncp   = (const int*)d_in[4];
    int F = in_sizes[2] / 3;
    int E = in_sizes[3] / 2;
    int P = in_sizes[4] / 4;

    Keys keys;
    // skey = key(42) -> (0, 42); fold_in(skey, 0/1)
    unsigned pk0, pk1, tk0, tk1;
    tf2x32(0u, 42u, 0u, 0u, pk0, pk1);
    tf2x32(0u, 42u, 0u, 1u, tk0, tk1);
    for (int grp = 0; grp < 2; grp++) {
        unsigned K0 = grp ? tk0 : pk0;
        unsigned K1 = grp ? tk1 : pk1;
        for (int b = 0; b < 8; b++) {
            // split(key, 8)[b] = tf(key, (0, b))  (fold-like split)
            unsigned mk0, mk1;
            tf2x32(K0, K1, 0u, (unsigned)b, mk0, mk1);
            // kf, kb = split(mesh_key, 2)
            unsigned f0, f1, b0, b1;
            tf2x32(mk0, mk1, 0u, 0u, f0, f1);
            tf2x32(mk0, mk1, 0u, 1u, b0, b1);
            int m = grp * 8 + b;
            keys.kf0[m] = f0; keys.kf1[m] = f1;
            keys.kb0[m] = b0; keys.kb1[m] = b1;
        }
    }

    k_zero<<<512, 256>>>();
    dim3 glog((F + 255) / 256, NM);
    k_logits<<<glog, 256>>>(vp, vt, faces, F);
    k_lmax<<<NM, 256>>>(F);
    k_categorical<<<NM * NS, 256>>>(keys, F);
    k_sample<<<(NM * NS + 255) / 256, 256>>>(keys, vp, vt, faces);
    k_chamfer<<<dim3(NB, 2, NS / 256), 256>>>();
    k_edge<<<2048, 256>>>(vp, edges, E);
    k_normal<<<2048, 256>>>(vp, ncp, P);
    k_lap_scatter<<<2048, 256>>>(vp, edges, E);
    k_lap_reduce<<<2048, 256>>>(vp);
    k_final<<<1, 1>>>((float*)d_out, E, P);
}

// round 15
// speedup vs baseline: 1.2666x; 1.0068x over previous
#include <cuda_runtime.h>
#include <stdint.h>
#include <math.h>

// ---------------------------------------------------------------------------
// Problem constants (G=256 grid, B=8 batches, 2048 samples)
// ---------------------------------------------------------------------------
#define NB 8            // batches
#define NM 16           // meshes = 8 pred + 8 targ
#define NV 65536        // vertices per mesh (G*G)
#define NS 2048         // samples per mesh
#define MAXF 131072     // capacity for faces (actual F = 130050)

// ---------------------------------------------------------------------------
// Scratch (static __device__ globals; no allocations allowed)
// ---------------------------------------------------------------------------
static __device__ float  g_logits[NM * MAXF];
static __device__ float  g_lmax[NM];
static __device__ int    g_fidx[NM * NS];
static __device__ float  g_samples[NM * NS * 3];
static __device__ double g_acc[4];               // 0:chamfer 1:edge 2:normal 3:lap
static __device__ float  g_nsum[NB * NV * 3];
static __device__ float  g_deg[NV];

struct Keys {
    unsigned kf0[NM], kf1[NM];   // categorical keys per mesh
    unsigned kb0[NM], kb1[NM];   // barycentric-uv keys per mesh
};

// ---------------------------------------------------------------------------
// Threefry-2x32 (exact JAX PRNG), host + device
// ---------------------------------------------------------------------------
__host__ __device__ __forceinline__ unsigned rotl32(unsigned x, int r) {
#ifdef __CUDA_ARCH__
    return __funnelshift_l(x, x, r);
#else
    return (x << r) | (x >> (32 - r));
#endif
}

__host__ __device__ __forceinline__ void tf2x32(unsigned k0, unsigned k1,
                                                unsigned c0, unsigned c1,
                                                unsigned &o0, unsigned &o1) {
    unsigned ks2 = k0 ^ k1 ^ 0x1BD11BDAu;
    unsigned x0 = c0 + k0, x1 = c1 + k1;
#define TFR(r) { x0 += x1; x1 = rotl32(x1, r); x1 ^= x0; }
    TFR(13) TFR(15) TFR(26) TFR(6)
    x0 += k1;  x1 += ks2 + 1u;
    TFR(17) TFR(29) TFR(16) TFR(24)
    x0 += ks2; x1 += k0 + 2u;
    TFR(13) TFR(15) TFR(26) TFR(6)
    x0 += k0;  x1 += k1 + 3u;
    TFR(17) TFR(29) TFR(16) TFR(24)
    x0 += k1;  x1 += ks2 + 4u;
    TFR(13) TFR(15) TFR(26) TFR(6)
    x0 += ks2; x1 += k0 + 5u;
#undef TFR
    o0 = x0; o1 = x1;
}

// Partitionable-mode 32-bit draw: counter (0, idx), output = o0 ^ o1.
__device__ __forceinline__ unsigned tf_bits32(unsigned k0, unsigned k1, unsigned idx) {
    unsigned o0, o1;
    tf2x32(k0, k1, 0u, idx, o0, o1);
    return o0 ^ o1;
}

__device__ __forceinline__ float bits_to_unit(unsigned b) {
    // JAX uniform bit manipulation: (bits>>9 | 0x3f800000) as float - 1
    // == (b >> 9) * 2^-23 exactly.
    return __uint_as_float((b >> 9) | 0x3f800000u) - 1.0f;
}

// Integer screen threshold from Gumbel-score slack t = best - lmax - 1e-3:
// bth = (floor(uth*2^23)+1) << 9, where uth = exp(-exp(-t)) - 8e-6.
// Conservative: u = (bits>>9)*2^-23 exactly and is strictly monotone in bits,
// so "u > uth" == "bits >= bth"; the 8e-6 slack (~67 mantissa ulps) dominates
// the 0.5-ulp conversion rounding -> no false negatives (validated in R4).
__device__ __forceinline__ unsigned bth_from_t(float t) {
    if (t >= 16.0f) return 0xFFFFFFFFu;
    float uth = expf(-expf(-t)) - 8e-6f;
    float mf = uth * 8388608.0f;               // uth * 2^23
    if (mf <= 0.0f)            return 0u;
    if (mf >= 8388607.0f)      return 0xFFFFFFFFu;
    return ((unsigned)mf + 1u) << 9;           // trunc == floor (mf > 0)
}

// ---------------------------------------------------------------------------
// Generic double block reduce (blockDim.x == 256)
// ---------------------------------------------------------------------------
__device__ double blockReduceSum(double v) {
    __shared__ double sm[32];
    int lane = threadIdx.x & 31, wid = threadIdx.x >> 5;
    for (int o = 16; o > 0; o >>= 1) v += __shfl_down_sync(0xffffffffu, v, o);
    if (lane == 0) sm[wid] = v;
    __syncthreads();
    v = (threadIdx.x < 8) ? sm[threadIdx.x] : 0.0;
    if (wid == 0)
        for (int o = 4; o > 0; o >>= 1) v += __shfl_down_sync(0xffffffffu, v, o);
    return v;
}

// ---------------------------------------------------------------------------
// K0: zero accumulators + laplacian scratch
// ---------------------------------------------------------------------------
__global__ void k_zero() {
    int i = blockIdx.x * blockDim.x + threadIdx.x;
    int stride = gridDim.x * blockDim.x;
    if (i < 4) g_acc[i] = 0.0;
    for (int t = i; t < NB * NV * 3; t += stride) g_nsum[t] = 0.0f;
    for (int t = i; t < NV; t += stride) g_deg[t] = 0.0f;
}

// ---------------------------------------------------------------------------
// K1: per-mesh per-face log(area + 1e-12)
// ---------------------------------------------------------------------------
__global__ void k_logits(const float* __restrict__ vp, const float* __restrict__ vt,
                         const int* __restrict__ faces, int F) {
    int f = blockIdx.x * blockDim.x + threadIdx.x;
    int m = blockIdx.y;
    if (f >= F) return;
    const float* v = (m < NB) ? (vp + (size_t)m * NV * 3)
                              : (vt + (size_t)(m - NB) * NV * 3);
    int a = faces[3*f], b = faces[3*f+1], c = faces[3*f+2];
    float ax = v[3*a], ay = v[3*a+1], az = v[3*a+2];
    float e1x = v[3*b]-ax, e1y = v[3*b+1]-ay, e1z = v[3*b+2]-az;
    float e2x = v[3*c]-ax, e2y = v[3*c+1]-ay, e2z = v[3*c+2]-az;
    float cx = e1y*e2z - e1z*e2y;
    float cy = e1z*e2x - e1x*e2z;
    float cz = e1x*e2y - e1y*e2x;
    float area = 0.5f * sqrtf(cx*cx + cy*cy + cz*cz);
    g_logits[m * MAXF + f] = logf(area + 1e-12f);
}

// K1b: per-mesh max logit
__global__ void k_lmax(int F) {
    __shared__ float sm[256];
    int m = blockIdx.x;
    float mx = -INFINITY;
    for (int f = threadIdx.x; f < F; f += 256) mx = fmaxf(mx, g_logits[m*MAXF + f]);
    sm[threadIdx.x] = mx; __syncthreads();
    for (int o = 128; o > 0; o >>= 1) {
        if (threadIdx.x < o) sm[threadIdx.x] = fmaxf(sm[threadIdx.x], sm[threadIdx.x + o]);
        __syncthreads();
    }
    if (threadIdx.x == 0) g_lmax[m] = sm[0];
}

// ---------------------------------------------------------------------------
// K2: categorical sampling — THE hot kernel (partitionable threefry).
// One block per (mesh m, row i in [0,2048)). Element (i,f) draws bits from
// counter (0, i*F+f), bits = o0^o1.
//
// R14 (warp-shared screen, -20%) + R4 integer screen: the hot path is now
// threefry + ONE integer compare (bits >= bth) — the bits->float conversion
// (SHF+LOP3+FADD) is deleted from the per-element path and happens only on
// rare candidate entries. bth is recomputed from the WARP-max best every 16
// iterations (butterfly SHFL+FMAX) and on private record updates; both are
// conservative w.r.t. the true argmax (threshold from a lower bound on the
// final max, minus slack), so the selected index is bit-identical.
// ---------------------------------------------------------------------------
__global__ __launch_bounds__(256) void k_categorical(Keys keys, int F) {
    int bid = blockIdx.x;
    int m = bid >> 11;          // 2048 rows per mesh
    int i = bid & 2047;
    unsigned k0 = keys.kf0[m], k1 = keys.kf1[m];
    const float* __restrict__ logits = g_logits + m * MAXF;
    float lmax = g_lmax[m];
    unsigned base = (unsigned)i * (unsigned)F;
    const float TINY = 1.1754944e-38f;

    float best = -INFINITY;
    int bf = 0;
    unsigned bth = 0u;          // accept-all initially

// one element; integer screen, exact Gumbel only for candidates
#define ELEM(ff) { \
    unsigned bits = tf_bits32(k0, k1, base + (unsigned)(ff)); \
    if (bits >= bth) { \
        float u = bits_to_unit(bits); \
        float s = -logf(-logf(fmaxf(u, TINY))) + logits[(ff)]; \
        if (s > best) { \
            best = s; bf = (ff); \
            bth = bth_from_t(best - lmax - 1e-3f); \
        } \
    } }

    int nmin = F >> 8;          // floor(F/256): iterations ALL threads have
    int nchunk = nmin >> 4;     // full 16-iteration warp-uniform chunks
    int rem = nmin & 15;
    int f = threadIdx.x;

    for (int c = 0; c < nchunk; ++c) {
#pragma unroll 4
        for (int j = 0; j < 16; ++j, f += 256) ELEM(f);
        // warp-shared threshold refresh (full warp active: chunks uniform)
        float wb = best;
#pragma unroll
        for (int o = 16; o > 0; o >>= 1)
            wb = fmaxf(wb, __shfl_xor_sync(0xffffffffu, wb, o));
        bth = bth_from_t(wb - lmax - 1e-3f);
    }
#pragma unroll 4
    for (int j = 0; j < rem; ++j, f += 256) ELEM(f);
    for (; f < F; f += 256) ELEM(f);   // per-thread tail (<=1 element)
#undef ELEM

    __shared__ float sv[256];
    __shared__ int   si[256];
    sv[threadIdx.x] = best; si[threadIdx.x] = bf;
    __syncthreads();
    for (int o = 128; o > 0; o >>= 1) {
        if (threadIdx.x < o) {
            float v2 = sv[threadIdx.x + o]; int i2 = si[threadIdx.x + o];
            if (v2 > sv[threadIdx.x] ||
                (v2 == sv[threadIdx.x] && i2 < si[threadIdx.x])) {
                sv[threadIdx.x] = v2; si[threadIdx.x] = i2;
            }
        }
        __syncthreads();
    }
    if (threadIdx.x == 0) g_fidx[m * NS + i] = si[0];
}

// ---------------------------------------------------------------------------
// K3: barycentric uv draws + point sampling (partitionable threefry)
// ---------------------------------------------------------------------------
__global__ void k_sample(Keys keys, const float* __restrict__ vp,
                         const float* __restrict__ vt, const int* __restrict__ faces) {
    int idx = blockIdx.x * blockDim.x + threadIdx.x;
    if (idx >= NM * NS) return;
    int m = idx / NS, s = idx % NS;
    unsigned k0 = keys.kb0[m], k1 = keys.kb1[m];
    // uv element (s, e) has flat index 2s+e in the (2048, 2) stream
    float u0 = bits_to_unit(tf_bits32(k0, k1, 2u * (unsigned)s));
    float u1 = bits_to_unit(tf_bits32(k0, k1, 2u * (unsigned)s + 1u));
    float su = sqrtf(u0);
    float w0 = 1.0f - su, w1 = su * (1.0f - u1), w2 = su * u1;
    int f = g_fidx[idx];
    const float* v = (m < NB) ? (vp + (size_t)m * NV * 3)
                              : (vt + (size_t)(m - NB) * NV * 3);
    int a = faces[3*f], b = faces[3*f+1], c = faces[3*f+2];
#pragma unroll
    for (int d = 0; d < 3; d++)
        g_samples[idx*3 + d] = w0 * v[3*a+d] + w1 * v[3*b+d] + w2 * v[3*c+d];
}

// ---------------------------------------------------------------------------
// K4: chamfer (both directions via blockIdx.y)
// ---------------------------------------------------------------------------
__global__ __launch_bounds__(256) void k_chamfer() {
    __shared__ float ys[NS * 3];
    int b = blockIdx.x, dir = blockIdx.y, chunk = blockIdx.z;
    int mx = (dir == 0) ? b : b + NB;
    int my = (dir == 0) ? b + NB : b;
    const float* X = g_samples + (size_t)mx * NS * 3;
    const float* Y = g_samples + (size_t)my * NS * 3;
    for (int t = threadIdx.x; t < NS * 3; t += 256) ys[t] = Y[t];
    __syncthreads();
    int s = chunk * 256 + threadIdx.x;
    float x0 = X[3*s], x1 = X[3*s+1], x2 = X[3*s+2];
    float mn = INFINITY;
    for (int j = 0; j < NS; j++) {
        float d0 = x0 - ys[3*j], d1 = x1 - ys[3*j+1], d2 = x2 - ys[3*j+2];
        mn = fminf(mn, d0*d0 + d1*d1 + d2*d2);
    }
    double v = blockReduceSum((double)mn);
    if (threadIdx.x == 0) atomicAdd(&g_acc[0], v);
}

// ---------------------------------------------------------------------------
// K5: edge loss
// ---------------------------------------------------------------------------
__global__ void k_edge(const float* __restrict__ vp, const int* __restrict__ edges, int E) {
    long total = (long)NB * E;
    double local = 0.0;
    for (long idx = (long)blockIdx.x * blockDim.x + threadIdx.x; idx < total;
         idx += (long)gridDim.x * blockDim.x) {
        int b = (int)(idx / E), e = (int)(idx % E);
        const float* v = vp + (size_t)b * NV * 3;
        int e0 = edges[2*e], e1 = edges[2*e+1];
        float dx = v[3*e0]-v[3*e1], dy = v[3*e0+1]-v[3*e1+1], dz = v[3*e0+2]-v[3*e1+2];
        local += (double)(dx*dx + dy*dy + dz*dz);
    }
    double v = blockReduceSum(local);
    if (threadIdx.x == 0) atomicAdd(&g_acc[1], v);
}

// ---------------------------------------------------------------------------
// K6: normal consistency
// ---------------------------------------------------------------------------
__global__ void k_normal(const float* __restrict__ vp, const int* __restrict__ ncp, int P) {
    long total = (long)NB * P;
    double local = 0.0;
    for (long idx = (long)blockIdx.x * blockDim.x + threadIdx.x; idx < total;
         idx += (long)gridDim.x * blockDim.x) {
        int b = (int)(idx / P), p = (int)(idx % P);
        const float* v = vp + (size_t)b * NV * 3;
        int i0 = ncp[4*p], i1 = ncp[4*p+1], ia = ncp[4*p+2], ib = ncp[4*p+3];
        float v0x = v[3*i0], v0y = v[3*i0+1], v0z = v[3*i0+2];
        float ex = v[3*i1]-v0x, ey = v[3*i1+1]-v0y, ez = v[3*i1+2]-v0z;
        float Ax = v[3*ia]-v0x, Ay = v[3*ia+1]-v0y, Az = v[3*ia+2]-v0z;
        float Bx = v[3*ib]-v0x, By = v[3*ib+1]-v0y, Bz = v[3*ib+2]-v0z;
        float n0x = ey*Az - ez*Ay, n0y = ez*Ax - ex*Az, n0z = ex*Ay - ey*Ax;
        float c1x = ey*Bz - ez*By, c1y = ez*Bx - ex*Bz, c1z = ex*By - ey*Bx;
        float dot = -(n0x*c1x + n0y*c1y + n0z*c1z);   // n1 = -cross(e, b-v0)
        float l0 = sqrtf(n0x*n0x + n0y*n0y + n0z*n0z);
        float l1 = sqrtf(c1x*c1x + c1y*c1y + c1z*c1z);
        float cosv = dot / (fmaxf(l0, 1e-8f) * fmaxf(l1, 1e-8f));
        local += (double)(1.0f - cosv);
    }
    double v = blockReduceSum(local);
    if (threadIdx.x == 0) atomicAdd(&g_acc[2], v);
}

// ---------------------------------------------------------------------------
// K7/K8: uniform laplacian
// ---------------------------------------------------------------------------
__global__ void k_lap_scatter(const float* __restrict__ vp, const int* __restrict__ edges, int E) {
    long total = (long)NB * E;
    for (long idx = (long)blockIdx.x * blockDim.x + threadIdx.x; idx < total;
         idx += (long)gridDim.x * blockDim.x) {
        int b = (int)(idx / E), e = (int)(idx % E);
        int e0 = edges[2*e], e1 = edges[2*e+1];
        const float* v = vp + (size_t)b * NV * 3;
#pragma unroll
        for (int c = 0; c < 3; c++) {
            atomicAdd(&g_nsum[((size_t)b*NV + e0)*3 + c], v[3*e1 + c]);
            atomicAdd(&g_nsum[((size_t)b*NV + e1)*3 + c], v[3*e0 + c]);
        }
        if (b == 0) {
            atomicAdd(&g_deg[e0], 1.0f);
            atomicAdd(&g_deg[e1], 1.0f);
        }
    }
}

__global__ void k_lap_reduce(const float* __restrict__ vp) {
    long total = (long)NB * NV;
    double local = 0.0;
    for (long idx = (long)blockIdx.x * blockDim.x + threadIdx.x; idx < total;
         idx += (long)gridDim.x * blockDim.x) {
        int b = (int)(idx / NV), vi = (int)(idx % NV);
        float dg = fmaxf(g_deg[vi], 1.0f);
        const float* v = vp + ((size_t)b * NV + vi) * 3;
        const float* ns = g_nsum + ((size_t)b * NV + vi) * 3;
        float lx = ns[0]/dg - v[0];
        float ly = ns[1]/dg - v[1];
        float lz = ns[2]/dg - v[2];
        local += (double)sqrtf(lx*lx + ly*ly + lz*lz);
    }
    double v = blockReduceSum(local);
    if (threadIdx.x == 0) atomicAdd(&g_acc[3], v);
}

// ---------------------------------------------------------------------------
// K9: finalize
// ---------------------------------------------------------------------------
__global__ void k_final(float* out, int E, int P) {
    double ch = g_acc[0] / (double)(NB * NS);       // both direction means summed
    double ed = g_acc[1] / ((double)NB * (double)E);
    double nr = g_acc[2] / ((double)NB * (double)P);
    double lp = g_acc[3] / ((double)NB * (double)NV);
    out[0] = (float)(ch + ed + 0.1 * nr + 0.1 * lp);
    out[1] = (float)ch;
    out[2] = (float)ed;
    out[3] = (float)nr;
    out[4] = (float)lp;
}

// ---------------------------------------------------------------------------
// Host: JAX key derivation, PARTITIONABLE threefry semantics:
//   fold_in(key, d)     = tf(key, (0, d))            -> (o0, o1)
//   split(key, n)[i]    = tf(key, (0, i))            -> (o0, o1)   (fold-like)
//   random_bits32[i]    = o0 ^ o1 of tf(key, (0, i))
// ---------------------------------------------------------------------------
extern "C" void kernel_launch(void* const* d_in, const int* in_sizes, int n_in,
                              void* d_out, int out_size) {
    const float* vp    = (const float*)d_in[0];
    const float* vt    = (const float*)d_in[1];
    const int*   faces = (const int*)d_in[2];
    const int*   edges = (const int*)d_in[3];
    const int*   ncp   = (const int*)d_in[4];
    int F = in_sizes[2] / 3;
    int E = in_sizes[3] / 2;
    int P = in_sizes[4] / 4;

    Keys keys;
    // skey = key(42) -> (0, 42); fold_in(skey, 0/1)
    unsigned pk0, pk1, tk0, tk1;
    tf2x32(0u, 42u, 0u, 0u, pk0, pk1);
    tf2x32(0u, 42u, 0u, 1u, tk0, tk1);
    for (int grp = 0; grp < 2; grp++) {
        unsigned K0 = grp ? tk0 : pk0;
        unsigned K1 = grp ? tk1 : pk1;
        for (int b = 0; b < 8; b++) {
            // split(key, 8)[b] = tf(key, (0, b))  (fold-like split)
            unsigned mk0, mk1;
            tf2x32(K0, K1, 0u, (unsigned)b, mk0, mk1);
            // kf, kb = split(mesh_key, 2)
            unsigned f0, f1, b0, b1;
            tf2x32(mk0, mk1, 0u, 0u, f0, f1);
            tf2x32(mk0, mk1, 0u, 1u, b0, b1);
            int m = grp * 8 + b;
            keys.kf0[m] = f0; keys.kf1[m] = f1;
            keys.kb0[m] = b0; keys.kb1[m] = b1;
        }
    }

    k_zero<<<512, 256>>>();
    dim3 glog((F + 255) / 256, NM);
    k_logits<<<glog, 256>>>(vp, vt, faces, F);
    k_lmax<<<NM, 256>>>(F);
    k_categorical<<<NM * NS, 256>>>(keys, F);
    k_sample<<<(NM * NS + 255) / 256, 256>>>(keys, vp, vt, faces);
    k_chamfer<<<dim3(NB, 2, NS / 256), 256>>>();
    k_edge<<<2048, 256>>>(vp, edges, E);
    k_normal<<<2048, 256>>>(vp, ncp, P);
    k_lap_scatter<<<2048, 256>>>(vp, edges, E);
    k_lap_reduce<<<2048, 256>>>(vp);
    k_final<<<1, 1>>>((float*)d_out, E, P);
}